// round 16
// baseline (speedup 1.0000x reference)
#include <cuda_runtime.h>
#include <cuda_fp16.h>
#include <cstdint>

#define B_SZ 8192
#define M_SZ 64
#define D_SZ 256
#define KX   512    // Xh layout: [h | r] fp16

#define NCHUNK 4
#define CB     (B_SZ / NCHUNK)   // 2048 samples per chunk

// scratch (static device arrays — no allocation)
__device__ __align__(256) float  g_r[B_SZ * D_SZ];            // 8 MB
__device__ __align__(256) __half g_Xh[(size_t)B_SZ * KX];     // 8 MB
__device__ __align__(256) __half g_Wh[256 * KX];              // 256 KB

// ---------------------------------------------------------------------------
// helpers
// ---------------------------------------------------------------------------
__device__ __forceinline__ void cp_async16(void* smem_ptr, const void* gptr) {
    unsigned sa = (unsigned)__cvta_generic_to_shared(smem_ptr);
    asm volatile("cp.async.cg.shared.global [%0], [%1], 16;\n" :: "r"(sa), "l"(gptr));
}
__device__ __forceinline__ void cp_commit() {
    asm volatile("cp.async.commit_group;\n");
}
template<int N> __device__ __forceinline__ void cp_wait() {
    asm volatile("cp.async.wait_group %0;\n" :: "n"(N));
}
__device__ __forceinline__ void ldsm_x4(uint32_t r[4], const void* p) {
    unsigned a = (unsigned)__cvta_generic_to_shared(p);
    asm volatile("ldmatrix.sync.aligned.m8n8.x4.shared.b16 {%0,%1,%2,%3}, [%4];"
                 : "=r"(r[0]), "=r"(r[1]), "=r"(r[2]), "=r"(r[3]) : "r"(a));
}
__device__ __forceinline__ uint32_t packh2(float x, float y) {
    __half2 t = __floats2half2_rn(x, y);
    return *(uint32_t*)&t;
}

// ---------------------------------------------------------------------------
// Kernel A (r15-proven): warp-per-sample ragged attention, chunked by base.
// chunk==0, blocks 0..255 also fold the fp16 W concat conversion.
// ---------------------------------------------------------------------------
struct Grp { float4 v[4][2]; };

__global__ __launch_bounds__(128, 4)
void attn_r_kernel(const float* __restrict__ h_tilde,
                   const float* __restrict__ mem,
                   const int* __restrict__ lengths,
                   const float* __restrict__ Wg_w,
                   const float* __restrict__ Ug_w,
                   int sbase) {
    const int tid  = threadIdx.x;
    const int warp = tid >> 5;
    const int lane = tid & 31;
    const int blk  = blockIdx.x;

    // folded W conversion (chunk 0 only)
    if (sbase == 0 && blk < 256) {
        const int n  = blk;
        const int j0 = tid * 2;
        const float w0 = (j0 < 256) ? Wg_w[n * 256 + j0]
                                    : Ug_w[n * 256 + (j0 - 256)];
        const float w1 = (j0 + 1 < 256) ? Wg_w[n * 256 + j0 + 1]
                                        : Ug_w[n * 256 + (j0 + 1 - 256)];
        *(uint32_t*)(g_Wh + (size_t)n * KX + j0) = packh2(w0, w1);
        const int j1 = j0 + 256;
        const float w2 = (j1 < 256) ? Wg_w[n * 256 + j1]
                                    : Ug_w[n * 256 + (j1 - 256)];
        const float w3 = (j1 + 1 < 256) ? Wg_w[n * 256 + j1 + 1]
                                        : Ug_w[n * 256 + (j1 + 1 - 256)];
        *(uint32_t*)(g_Wh + (size_t)n * KX + j1) = packh2(w2, w3);
    }

    const int b   = sbase + blk * 4 + warp;
    const int len = lengths[b];

    const float4* hp = (const float4*)(h_tilde + (size_t)b * D_SZ);
    const float4 ha = hp[lane * 2];
    const float4 hb = hp[lane * 2 + 1];

    float4 r0 = make_float4(0.f, 0.f, 0.f, 0.f);
    float4 r1 = make_float4(0.f, 0.f, 0.f, 0.f);

    if (len > 0) {
        const float4* base = (const float4*)(mem + (size_t)b * M_SZ * D_SZ);
        float Mrun = -3.0e38f, Srun = 0.f;

        Grp A, Bf;

        auto loadg = [&](Grp& R, int g) {
#pragma unroll
            for (int i = 0; i < 4; ++i) {
                const int m = g * 4 + i;
                R.v[i][0] = make_float4(0.f, 0.f, 0.f, 0.f);
                R.v[i][1] = make_float4(0.f, 0.f, 0.f, 0.f);
                if (m < len) {
                    const float4* rp = base + (size_t)m * 64 + lane * 2;
                    R.v[i][0] = rp[0];
                    R.v[i][1] = rp[1];
                }
            }
        };

        auto process = [&](const Grp& R, int g) {
            float sc[4];
#pragma unroll
            for (int i = 0; i < 4; ++i) {
                const float4 a = R.v[i][0];
                const float4 c = R.v[i][1];
                float acc = a.x * ha.x;
                acc = fmaf(a.y, ha.y, acc);
                acc = fmaf(a.z, ha.z, acc);
                acc = fmaf(a.w, ha.w, acc);
                acc = fmaf(c.x, hb.x, acc);
                acc = fmaf(c.y, hb.y, acc);
                acc = fmaf(c.z, hb.z, acc);
                acc = fmaf(c.w, hb.w, acc);
#pragma unroll
                for (int off = 16; off; off >>= 1)
                    acc += __shfl_xor_sync(0xffffffffu, acc, off);
                sc[i] = (g * 4 + i < len) ? acc : -1e9f;
            }
            const float cmax = fmaxf(fmaxf(sc[0], sc[1]), fmaxf(sc[2], sc[3]));
            const float nM   = fmaxf(Mrun, cmax);
            const float corr = __expf(Mrun - nM);
            const float e0 = __expf(sc[0] - nM);
            const float e1 = __expf(sc[1] - nM);
            const float e2 = __expf(sc[2] - nM);
            const float e3 = __expf(sc[3] - nM);
            Srun = Srun * corr + (e0 + e1) + (e2 + e3);
            Mrun = nM;
            r0.x = fmaf(e0, R.v[0][0].x, fmaf(e1, R.v[1][0].x, fmaf(e2, R.v[2][0].x, fmaf(e3, R.v[3][0].x, r0.x * corr))));
            r0.y = fmaf(e0, R.v[0][0].y, fmaf(e1, R.v[1][0].y, fmaf(e2, R.v[2][0].y, fmaf(e3, R.v[3][0].y, r0.y * corr))));
            r0.z = fmaf(e0, R.v[0][0].z, fmaf(e1, R.v[1][0].z, fmaf(e2, R.v[2][0].z, fmaf(e3, R.v[3][0].z, r0.z * corr))));
            r0.w = fmaf(e0, R.v[0][0].w, fmaf(e1, R.v[1][0].w, fmaf(e2, R.v[2][0].w, fmaf(e3, R.v[3][0].w, r0.w * corr))));
            r1.x = fmaf(e0, R.v[0][1].x, fmaf(e1, R.v[1][1].x, fmaf(e2, R.v[2][1].x, fmaf(e3, R.v[3][1].x, r1.x * corr))));
            r1.y = fmaf(e0, R.v[0][1].y, fmaf(e1, R.v[1][1].y, fmaf(e2, R.v[2][1].y, fmaf(e3, R.v[3][1].y, r1.y * corr))));
            r1.z = fmaf(e0, R.v[0][1].z, fmaf(e1, R.v[1][1].z, fmaf(e2, R.v[2][1].z, fmaf(e3, R.v[3][1].z, r1.z * corr))));
            r1.w = fmaf(e0, R.v[0][1].w, fmaf(e1, R.v[1][1].w, fmaf(e2, R.v[2][1].w, fmaf(e3, R.v[3][1].w, r1.w * corr))));
        };

        const int ng = (len + 3) >> 2;
        loadg(A, 0);
        int g = 0;
        while (true) {
            if (g + 1 < ng) loadg(Bf, g + 1);
            process(A, g);
            ++g;
            if (g >= ng) break;
            if (g + 1 < ng) loadg(A, g + 1);
            process(Bf, g);
            ++g;
            if (g >= ng) break;
        }

        const float inv = 1.f / Srun;
        r0.x *= inv; r0.y *= inv; r0.z *= inv; r0.w *= inv;
        r1.x *= inv; r1.y *= inv; r1.z *= inv; r1.w *= inv;
    }

    // store r (fp32, for the epilogue)
    float* gr = g_r + (size_t)b * D_SZ + lane * 8;
    *(float4*)gr       = r0;
    *(float4*)(gr + 4) = r1;

    // emit Xh row: [h | r] fp16
    __half* xr = g_Xh + (size_t)b * KX + lane * 8;
    uint4 p;
    p.x = packh2(ha.x, ha.y); p.y = packh2(ha.z, ha.w);
    p.z = packh2(hb.x, hb.y); p.w = packh2(hb.z, hb.w);
    *(uint4*)(xr) = p;
    p.x = packh2(r0.x, r0.y); p.y = packh2(r0.z, r0.w);
    p.z = packh2(r1.x, r1.y); p.w = packh2(r1.z, r1.w);
    *(uint4*)(xr + 256) = p;
}

// ---------------------------------------------------------------------------
// Kernel B (r15-proven): fp16 tensor-core GEMM, K=512 single pass.
// BM=128, BN=128, BK=64, 512 threads, 3-stage cp.async, chunked by mbase.
// ---------------------------------------------------------------------------
#define BM 128
#define BN 128
#define BK 64
#define LDSK 72
#define STG (BM * LDSK)

__device__ __forceinline__ void mma16816(float c[4], const uint32_t a[4],
                                         const uint32_t b0, const uint32_t b1) {
    asm volatile(
        "mma.sync.aligned.m16n8k16.row.col.f32.f16.f16.f32 "
        "{%0,%1,%2,%3}, {%4,%5,%6,%7}, {%8,%9}, {%0,%1,%2,%3};\n"
        : "+f"(c[0]), "+f"(c[1]), "+f"(c[2]), "+f"(c[3])
        : "r"(a[0]), "r"(a[1]), "r"(a[2]), "r"(a[3]), "r"(b0), "r"(b1));
}

__global__ __launch_bounds__(512)
void gate_gemm_f16(const float* __restrict__ h_tilde,
                   const float* __restrict__ Wg_b,
                   const float* __restrict__ Ug_b,
                   const float* __restrict__ b_g,
                   const int* __restrict__ lengths,
                   float* __restrict__ out,
                   int mbase) {
    extern __shared__ __align__(16) __half smem[];
    __half* sA = smem;
    __half* sB = smem + 3 * STG;

    const int tid  = threadIdx.x;
    const int warp = tid >> 5;
    const int lane = tid & 31;
    const int gq   = lane >> 2;
    const int t    = lane & 3;
    const int wm   = warp >> 2;
    const int wn   = warp & 3;
    const int bm0  = mbase + blockIdx.x * BM;
    const int bn0  = blockIdx.y * BN;

    float acc[2][4][4];
#pragma unroll
    for (int mt = 0; mt < 2; ++mt)
#pragma unroll
        for (int q = 0; q < 4; ++q)
#pragma unroll
            for (int i = 0; i < 4; ++i) acc[mt][q][i] = 0.f;

    const __half* gA = g_Xh + (size_t)bm0 * KX;
    const __half* gB = g_Wh + (size_t)bn0 * KX;

    const int lr = tid >> 2;
    const int c0 = (tid & 3) * 8;
    const int c1 = c0 + 32;

#pragma unroll
    for (int p = 0; p < 2; ++p) {
        const int ko = p * BK;
        cp_async16(sA + p * STG + lr * LDSK + c0, gA + (size_t)lr * KX + ko + c0);
        cp_async16(sA + p * STG + lr * LDSK + c1, gA + (size_t)lr * KX + ko + c1);
        cp_async16(sB + p * STG + lr * LDSK + c0, gB + (size_t)lr * KX + ko + c0);
        cp_async16(sB + p * STG + lr * LDSK + c1, gB + (size_t)lr * KX + ko + c1);
        cp_commit();
    }

    const int lmrow = lane & 15;
    const int lmcol = (lane >> 4) * 8;

    const int NKT = KX / BK;   // 8
    for (int kt = 0; kt < NKT; ++kt) {
        cp_wait<1>();
        __syncthreads();

        const int pc = kt + 2;
        if (pc < NKT) {
            const int st = pc % 3;
            const int ko = pc * BK;
            cp_async16(sA + st * STG + lr * LDSK + c0, gA + (size_t)lr * KX + ko + c0);
            cp_async16(sA + st * STG + lr * LDSK + c1, gA + (size_t)lr * KX + ko + c1);
            cp_async16(sB + st * STG + lr * LDSK + c0, gB + (size_t)lr * KX + ko + c0);
            cp_async16(sB + st * STG + lr * LDSK + c1, gB + (size_t)lr * KX + ko + c1);
        }
        cp_commit();

        const __half* A  = sA + (kt % 3) * STG;
        const __half* Bs = sB + (kt % 3) * STG;

#pragma unroll
        for (int ks = 0; ks < 4; ++ks) {
            uint32_t af[2][4], bf[2][4];
#pragma unroll
            for (int mt = 0; mt < 2; ++mt)
                ldsm_x4(af[mt],
                        A + (wm * 32 + mt * 16 + lmrow) * LDSK + ks * 16 + lmcol);
#pragma unroll
            for (int j = 0; j < 2; ++j)
                ldsm_x4(bf[j],
                        Bs + (wn * 32 + j * 16 + lmrow) * LDSK + ks * 16 + lmcol);
#pragma unroll
            for (int mt = 0; mt < 2; ++mt) {
#pragma unroll
                for (int j = 0; j < 2; ++j) {
                    mma16816(acc[mt][2 * j],     af[mt], bf[j][0], bf[j][2]);
                    mma16816(acc[mt][2 * j + 1], af[mt], bf[j][1], bf[j][3]);
                }
            }
        }
    }

    // fused epilogue
#pragma unroll
    for (int q = 0; q < 4; ++q) {
        const int n = bn0 + wn * 32 + (q >> 1) * 16 + (q & 1) * 8 + 2 * t;
        const float bi0 = Wg_b[n] + Ug_b[n] + b_g[n];
        const float bi1 = Wg_b[n + 1] + Ug_b[n + 1] + b_g[n + 1];
#pragma unroll
        for (int mt = 0; mt < 2; ++mt) {
#pragma unroll
            for (int h2 = 0; h2 < 2; ++h2) {
                const int row = bm0 + wm * 32 + mt * 16 + gq + 8 * h2;
                const bool has = lengths[row] > 0;
                const size_t base = (size_t)row * D_SZ + n;
                const float2 rv = *(const float2*)(g_r + base);
                const float2 hv = *(const float2*)(h_tilde + base);
                const float z0 = acc[mt][q][2 * h2 + 0] + bi0;
                const float z1 = acc[mt][q][2 * h2 + 1] + bi1;
                const float g0 = 1.f / (1.f + __expf(-z0));
                const float g1 = 1.f / (1.f + __expf(-z1));
                const float o0 = has ? (g0 * rv.x + (1.f - g0) * hv.x) : hv.x;
                const float o1 = has ? (g1 * rv.y + (1.f - g1) * hv.y) : hv.y;
                *(float2*)(out + base) = make_float2(o0, o1);
            }
        }
    }
}

// ---------------------------------------------------------------------------
// Launcher: chunked fork/join pipeline. attn chunks on the main stream,
// gemm chunks on a second stream gated by per-chunk events, joined at end.
// Stream/events created once (outside capture); per-call work is identical.
// ---------------------------------------------------------------------------
extern "C" void kernel_launch(void* const* d_in, const int* in_sizes, int n_in,
                              void* d_out, int out_size) {
    const float* h_tilde = (const float*)d_in[0];
    const float* mem     = (const float*)d_in[1];
    const int*   lengths = (const int*)d_in[2];
    const float* Wg_w    = (const float*)d_in[3];
    const float* Wg_b    = (const float*)d_in[4];
    const float* Ug_w    = (const float*)d_in[5];
    const float* Ug_b    = (const float*)d_in[6];
    const float* b_g     = (const float*)d_in[7];
    float* out = (float*)d_out;

    static cudaStream_t s2 = nullptr;
    static cudaEvent_t evA[NCHUNK];
    static cudaEvent_t evJ;
    if (s2 == nullptr) {
        cudaStreamCreateWithFlags(&s2, cudaStreamNonBlocking);
        for (int i = 0; i < NCHUNK; ++i)
            cudaEventCreateWithFlags(&evA[i], cudaEventDisableTiming);
        cudaEventCreateWithFlags(&evJ, cudaEventDisableTiming);
    }

    const int smem_b = 6 * STG * (int)sizeof(__half);  // 110592
    cudaFuncSetAttribute(gate_gemm_f16,
                         cudaFuncAttributeMaxDynamicSharedMemorySize, smem_b);

    dim3 gridB(CB / BM, D_SZ / BN);   // 16 x 2 per chunk

    for (int c = 0; c < NCHUNK; ++c) {
        attn_r_kernel<<<CB / 4, 128>>>(h_tilde, mem, lengths, Wg_w, Ug_w,
                                       c * CB);
        cudaEventRecord(evA[c], 0);
        cudaStreamWaitEvent(s2, evA[c], 0);
        gate_gemm_f16<<<gridB, 512, smem_b, s2>>>(h_tilde, Wg_b, Ug_b, b_g,
                                                  lengths, out, c * CB);
    }
    cudaEventRecord(evJ, s2);
    cudaStreamWaitEvent(0, evJ, 0);
}